// round 7
// baseline (speedup 1.0000x reference)
#include <cuda_runtime.h>
#include <cuda_bf16.h>
#include <math.h>
#include <stdint.h>

#define BB   8
#define NN   4096
#define MM   4096
#define KK   64

#define NTILES 4096            // 8 b * 32 nblk * 16 mblk  (tiles of 128n x 256m)

#define FINF __int_as_float(0x7F800000)

__device__ float g_min_m[BB * NN];
__device__ float g_min_n[BB * MM];
__device__ float g_x2[BB * NN];
__device__ float g_y2[BB * MM];

// Pre-converted, pre-swizzled 16 KB tile images (smem-ready, 128 rows each).
__device__ unsigned char g_xbf[BB * NN * 128];
__device__ unsigned char g_yhi[BB * MM * 128];
__device__ unsigned char g_ylo[BB * MM * 128];

__device__ __forceinline__ uint32_t s2u(const void* p) {
    uint32_t a;
    asm("{ .reg .u64 t; cvta.to.shared.u64 t, %1; cvt.u32.u64 %0, t; }"
        : "=r"(a) : "l"(p));
    return a;
}

#define SWZ(o) ((o) ^ (((o) >> 3) & 0x70))

// Stage layout: A [0,16K), BHI [16K,48K), BLO [48K,80K). Two stages.
#define STAGE    81920
#define OFF_BHI  16384
#define OFF_BLO  49152
#define SM_SROW  163840
#define SM_SCOL  164352
#define SMEM_SZ  165376

// ---------------------------------------------------------------------------
// Kernel 1: convert + swizzle-pack + norms + min-init. 16 lanes per row.
// ---------------------------------------------------------------------------
__global__ void prep_kernel(const float* __restrict__ x,
                            const float* __restrict__ y) {
    const int gid = blockIdx.x * blockDim.x + threadIdx.x;
    const int row = gid >> 4, k4 = gid & 15;
    const int R = BB * NN;
    const bool isx = row < R;
    const int r = isx ? row : row - R;

    const float4 v = ((const float4*)((isx ? x : y) + (size_t)r * KK))[k4];
    const uint32_t off = (uint32_t)(r >> 7) * 16384u +
                         SWZ((uint32_t)((r & 127) * 128 + k4 * 8));

    if (isx) {
        __nv_bfloat162 p01 = __floats2bfloat162_rn(v.x, v.y);
        __nv_bfloat162 p23 = __floats2bfloat162_rn(v.z, v.w);
        uint2 h;
        h.x = *reinterpret_cast<uint32_t*>(&p01);
        h.y = *reinterpret_cast<uint32_t*>(&p23);
        *(uint2*)(g_xbf + off) = h;
    } else {
        __nv_bfloat162 h01 = __floats2bfloat162_rn(v.x, v.y);
        __nv_bfloat162 h23 = __floats2bfloat162_rn(v.z, v.w);
        float r0 = v.x - __low2float(h01);
        float r1 = v.y - __high2float(h01);
        float r2 = v.z - __low2float(h23);
        float r3 = v.w - __high2float(h23);
        __nv_bfloat162 l01 = __floats2bfloat162_rn(r0, r1);
        __nv_bfloat162 l23 = __floats2bfloat162_rn(r2, r3);
        uint2 h, l;
        h.x = *reinterpret_cast<uint32_t*>(&h01);
        h.y = *reinterpret_cast<uint32_t*>(&h23);
        l.x = *reinterpret_cast<uint32_t*>(&l01);
        l.y = *reinterpret_cast<uint32_t*>(&l23);
        *(uint2*)(g_yhi + off) = h;
        *(uint2*)(g_ylo + off) = l;
    }

    float s = v.x * v.x + v.y * v.y + v.z * v.z + v.w * v.w;
    s += __shfl_xor_sync(~0u, s, 1);
    s += __shfl_xor_sync(~0u, s, 2);
    s += __shfl_xor_sync(~0u, s, 4);
    s += __shfl_xor_sync(~0u, s, 8);
    if (k4 == 0) {
        if (isx) { g_x2[r] = s; g_min_m[r] = FINF; }
        else     { g_y2[r] = s; g_min_n[r] = FINF; }
    }
}

__device__ __forceinline__ void mma16816(float* c, const uint32_t* a,
                                         const uint32_t* b) {
    asm volatile(
        "mma.sync.aligned.m16n8k16.row.col.f32.bf16.bf16.f32 "
        "{%0,%1,%2,%3}, {%4,%5,%6,%7}, {%8,%9}, {%0,%1,%2,%3};"
        : "+f"(c[0]), "+f"(c[1]), "+f"(c[2]), "+f"(c[3])
        : "r"(a[0]), "r"(a[1]), "r"(a[2]), "r"(a[3]), "r"(b[0]), "r"(b[1]));
}

__device__ __forceinline__ void cp16(uint32_t dst, const void* src) {
    asm volatile("cp.async.cg.shared.global [%0], [%1], 16;"
                 :: "r"(dst), "l"(src) : "memory");
}

// ---------------------------------------------------------------------------
// Kernel 2: persistent, double-buffered. 128x256 tile per iteration.
// 16 warps: wn = w>>3 (two 64-row bands), wm = w&7 (eight 32-col bands).
// ---------------------------------------------------------------------------
extern __shared__ char smem[];

__device__ __forceinline__ void prefetch_tile(uint32_t sb, int stage, int tl,
                                              int t) {
    const int b = tl >> 9, rem = tl & 511, nb = rem >> 4, mb = rem & 15;
    const unsigned char* a = g_xbf + (size_t)(b * 32 + nb) * 16384;
    const unsigned char* h = g_yhi + (size_t)(b * 32 + mb * 2) * 16384;
    const unsigned char* l = g_ylo + (size_t)(b * 32 + mb * 2) * 16384;
    const uint32_t dst = sb + stage * STAGE;
    const uint32_t o = (uint32_t)t * 16;
    cp16(dst + o, a + o);
    cp16(dst + o + 8192, a + o + 8192);
#pragma unroll
    for (int i = 0; i < 4; i++) {
        cp16(dst + OFF_BHI + o + i * 8192, h + o + i * 8192);
        cp16(dst + OFF_BLO + o + i * 8192, l + o + i * 8192);
    }
}

__global__ void __launch_bounds__(512, 1)
tile_hmma_kernel(int G) {
    const uint32_t sb = s2u(smem);
    const int t = threadIdx.x, lane = t & 31, w = t >> 5;
    const int wn = w >> 3;            // 0..1 : 64-row band
    const int wm = w & 7;             // 0..7 : 32-col band

    float* srow = (float*)(smem + SM_SROW);
    float* scol = (float*)(smem + SM_SCOL);

    // Per-lane ldmatrix base offsets (bytes, pre-swizzle).
    const int tq = lane >> 3, tr = lane & 7;
    uint32_t aOff[4], bOff[4];
#pragma unroll
    for (int mt = 0; mt < 4; mt++)
        aOff[mt] = (uint32_t)((wn * 64 + mt * 16 + (tq & 1) * 8 + tr) * 128 +
                              (tq >> 1) * 16);
    const int l16 = lane & 15;
#pragma unroll
    for (int nt = 0; nt < 4; nt++)
        bOff[nt] = (uint32_t)((wm * 32 + nt * 8 + (l16 & 7)) * 128 +
                              (l16 >> 3) * 16);

    int tid = blockIdx.x;
    if (tid >= NTILES) return;

    prefetch_tile(sb, 0, tid, t);
    asm volatile("cp.async.commit_group;" ::: "memory");

    int p = 0;
    for (; tid < NTILES; tid += G, p ^= 1) {
        const int nx = tid + G;
        if (nx < NTILES) prefetch_tile(sb, p ^ 1, nx, t);
        asm volatile("cp.async.commit_group;" ::: "memory");
        asm volatile("cp.async.wait_group 1;" ::: "memory");
        __syncthreads();

        if (t < 128) srow[t] = FINF;
        else if (t < 384) scol[t - 128] = FINF;

        const int b = tid >> 9, rem = tid & 511;
        const int n0 = (rem >> 4) * 128, m0 = (rem & 15) * 256;
        const uint32_t base = sb + p * STAGE;

        float acc[4][4][4];
#pragma unroll
        for (int i = 0; i < 4; i++)
#pragma unroll
            for (int j = 0; j < 4; j++)
#pragma unroll
                for (int e = 0; e < 4; e++) acc[i][j][e] = 0.f;

#pragma unroll
        for (int kk = 0; kk < 4; kk++) {
            const uint32_t kcol = kk * 32;
            uint32_t a[4][4];
#pragma unroll
            for (int mt = 0; mt < 4; mt++) {
                uint32_t addr = base + SWZ(aOff[mt] + kcol);
                asm volatile("ldmatrix.sync.aligned.m8n8.x4.shared.b16 "
                             "{%0,%1,%2,%3}, [%4];"
                             : "=r"(a[mt][0]), "=r"(a[mt][1]),
                               "=r"(a[mt][2]), "=r"(a[mt][3]) : "r"(addr));
            }
#pragma unroll
            for (int ph = 0; ph < 2; ph++) {
                const uint32_t bbase = base + (ph ? OFF_BLO : OFF_BHI);
                uint32_t bf[4][2];
#pragma unroll
                for (int nt = 0; nt < 4; nt++) {
                    uint32_t addr = bbase + SWZ(bOff[nt] + kcol);
                    asm volatile("ldmatrix.sync.aligned.m8n8.x2.shared.b16 "
                                 "{%0,%1}, [%2];"
                                 : "=r"(bf[nt][0]), "=r"(bf[nt][1]) : "r"(addr));
                }
#pragma unroll
                for (int mt = 0; mt < 4; mt++)
#pragma unroll
                    for (int nt = 0; nt < 4; nt++)
                        mma16816(acc[mt][nt], a[mt], bf[nt]);
            }
        }

        // Epilogue. Fragment (m16n8): e -> row l/4 + (e>>1)*8, col 2*(l%4)+(e&1)
        float x2r[8], y2c[8];
#pragma unroll
        for (int mt = 0; mt < 4; mt++)
#pragma unroll
            for (int s = 0; s < 2; s++)
                x2r[mt * 2 + s] = __ldg(
                    &g_x2[b * NN + n0 + wn * 64 + mt * 16 + (lane >> 2) + s * 8]);
#pragma unroll
        for (int nt = 0; nt < 4; nt++)
#pragma unroll
            for (int e = 0; e < 2; e++)
                y2c[nt * 2 + e] = __ldg(
                    &g_y2[b * MM + m0 + wm * 32 + nt * 8 + 2 * (lane & 3) + e]);

        float rowmin[8], colmin[8];
#pragma unroll
        for (int i = 0; i < 8; i++) { rowmin[i] = FINF; colmin[i] = FINF; }

#pragma unroll
        for (int mt = 0; mt < 4; mt++)
#pragma unroll
            for (int nt = 0; nt < 4; nt++)
#pragma unroll
                for (int e = 0; e < 4; e++) {
                    const int ri = mt * 2 + (e >> 1), cj = nt * 2 + (e & 1);
                    float v = -2.f * acc[mt][nt][e];
                    rowmin[ri] = fminf(rowmin[ri], v + y2c[cj]);
                    colmin[cj] = fminf(colmin[cj], v + x2r[ri]);
                }

#pragma unroll
        for (int off = 1; off <= 2; off <<= 1)
#pragma unroll
            for (int i = 0; i < 8; i++)
                rowmin[i] = fminf(rowmin[i],
                                  __shfl_xor_sync(~0u, rowmin[i], off));
#pragma unroll
        for (int off = 4; off <= 16; off <<= 1)
#pragma unroll
            for (int i = 0; i < 8; i++)
                colmin[i] = fminf(colmin[i],
                                  __shfl_xor_sync(~0u, colmin[i], off));

        __syncthreads();   // srow/scol init visible everywhere

        if ((lane & 3) == 0) {
#pragma unroll
            for (int mt = 0; mt < 4; mt++)
#pragma unroll
                for (int s = 0; s < 2; s++) {
                    int row = wn * 64 + mt * 16 + (lane >> 2) + s * 8;
                    float v = fmaxf(rowmin[mt * 2 + s] + x2r[mt * 2 + s], 0.f);
                    atomicMin((int*)&srow[row], __float_as_int(v));
                }
        }
        if (lane < 4) {
#pragma unroll
            for (int nt = 0; nt < 4; nt++)
#pragma unroll
                for (int e = 0; e < 2; e++) {
                    int col = wm * 32 + nt * 8 + 2 * lane + e;
                    float v = fmaxf(colmin[nt * 2 + e] + y2c[nt * 2 + e], 0.f);
                    atomicMin((int*)&scol[col], __float_as_int(v));
                }
        }
        __syncthreads();

        if (t < 128)
            atomicMin((int*)&g_min_m[b * NN + n0 + t], __float_as_int(srow[t]));
        else if (t < 384)
            atomicMin((int*)&g_min_n[b * MM + m0 + t - 128],
                      __float_as_int(scol[t - 128]));
    }
}

// ---------------------------------------------------------------------------
// Kernel 3: loss = sum(sqrt(mins)) / (B * 4096)
// ---------------------------------------------------------------------------
__global__ void reduce_kernel(float* __restrict__ out) {
    __shared__ float ssum[1024];
    int t = threadIdx.x;
    float s = 0.f;
    for (int i = t; i < BB * NN; i += 1024)
        s += sqrtf(g_min_m[i]) + sqrtf(g_min_n[i]);
    ssum[t] = s;
    __syncthreads();
#pragma unroll
    for (int off = 512; off > 0; off >>= 1) {
        if (t < off) ssum[t] += ssum[t + off];
        __syncthreads();
    }
    if (t == 0) out[0] = ssum[0] * (1.0f / (BB * NN));
}

// ---------------------------------------------------------------------------
extern "C" void kernel_launch(void* const* d_in, const int* in_sizes, int n_in,
                              void* d_out, int out_size) {
    const float* x = (const float*)d_in[0];
    const float* y = (const float*)d_in[1];
    float* out = (float*)d_out;

    static int nsm = 0;
    if (nsm == 0) {
        if (cudaDeviceGetAttribute(&nsm, cudaDevAttrMultiProcessorCount, 0)
                != cudaSuccess || nsm <= 0)
            nsm = 148;
        cudaFuncSetAttribute(tile_hmma_kernel,
                             cudaFuncAttributeMaxDynamicSharedMemorySize,
                             SMEM_SZ);
    }

    prep_kernel<<<(2 * BB * NN * 16) / 256, 256>>>(x, y);

    int G = nsm < NTILES ? nsm : NTILES;
    tile_hmma_kernel<<<G, 512, SMEM_SZ>>>(G);

    reduce_kernel<<<1, 1024>>>(out);
}

// round 9
// speedup vs baseline: 1.0632x; 1.0632x over previous
#include <cuda_runtime.h>
#include <cuda_bf16.h>
#include <math.h>
#include <stdint.h>

#define BB   8
#define NN   4096
#define MM   4096
#define KK   64

#define NTILES 8192            // 8 b * 32 nblk * 32 mblk (tiles 128n x 128m)

#define FINF __int_as_float(0x7F800000)

__device__ float g_min_m[BB * NN];
__device__ float g_min_n[BB * MM];
__device__ float g_x2[BB * NN];
__device__ float g_y2[BB * MM];

// Pre-converted, pre-swizzled 16 KB tile images (smem-ready, 128 rows each).
__device__ __align__(16384) unsigned char g_xbf[BB * NN * 128];
__device__ __align__(16384) unsigned char g_yhi[BB * MM * 128];
__device__ __align__(16384) unsigned char g_ylo[BB * MM * 128];

__device__ __forceinline__ uint32_t s2u(const void* p) {
    uint32_t a;
    asm("{ .reg .u64 t; cvta.to.shared.u64 t, %1; cvt.u32.u64 %0, t; }"
        : "=r"(a) : "l"(p));
    return a;
}

#define SWZ(o) ((o) ^ (((o) >> 3) & 0x70))

// Stage: A [0,16K) BHI [16K,32K) BLO [32K,48K). Two stages.
#define STAGE    49152
#define OFF_BHI  16384
#define OFF_BLO  32768
#define SMEM_SZ  98304

// ---------------------------------------------------------------------------
// Kernel 1: convert + swizzle-pack + norms + min-init. 16 lanes per row.
// ---------------------------------------------------------------------------
__global__ void prep_kernel(const float* __restrict__ x,
                            const float* __restrict__ y) {
    const int gid = blockIdx.x * blockDim.x + threadIdx.x;
    const int row = gid >> 4, k4 = gid & 15;
    const int R = BB * NN;
    const bool isx = row < R;
    const int r = isx ? row : row - R;

    const float4 v = ((const float4*)((isx ? x : y) + (size_t)r * KK))[k4];
    const uint32_t off = (uint32_t)(r >> 7) * 16384u +
                         SWZ((uint32_t)((r & 127) * 128 + k4 * 8));

    if (isx) {
        __nv_bfloat162 p01 = __floats2bfloat162_rn(v.x, v.y);
        __nv_bfloat162 p23 = __floats2bfloat162_rn(v.z, v.w);
        uint2 h;
        h.x = *reinterpret_cast<uint32_t*>(&p01);
        h.y = *reinterpret_cast<uint32_t*>(&p23);
        *(uint2*)(g_xbf + off) = h;
    } else {
        __nv_bfloat162 h01 = __floats2bfloat162_rn(v.x, v.y);
        __nv_bfloat162 h23 = __floats2bfloat162_rn(v.z, v.w);
        float r0 = v.x - __low2float(h01);
        float r1 = v.y - __high2float(h01);
        float r2 = v.z - __low2float(h23);
        float r3 = v.w - __high2float(h23);
        __nv_bfloat162 l01 = __floats2bfloat162_rn(r0, r1);
        __nv_bfloat162 l23 = __floats2bfloat162_rn(r2, r3);
        uint2 h, l;
        h.x = *reinterpret_cast<uint32_t*>(&h01);
        h.y = *reinterpret_cast<uint32_t*>(&h23);
        l.x = *reinterpret_cast<uint32_t*>(&l01);
        l.y = *reinterpret_cast<uint32_t*>(&l23);
        *(uint2*)(g_yhi + off) = h;
        *(uint2*)(g_ylo + off) = l;
    }

    float s = v.x * v.x + v.y * v.y + v.z * v.z + v.w * v.w;
    s += __shfl_xor_sync(~0u, s, 1);
    s += __shfl_xor_sync(~0u, s, 2);
    s += __shfl_xor_sync(~0u, s, 4);
    s += __shfl_xor_sync(~0u, s, 8);
    if (k4 == 0) {
        if (isx) { g_x2[r] = s; g_min_m[r] = FINF; }
        else     { g_y2[r] = s; g_min_n[r] = FINF; }
    }
}

__device__ __forceinline__ void mma16816(float* c, const uint32_t* a,
                                         const uint32_t* b) {
    asm volatile(
        "mma.sync.aligned.m16n8k16.row.col.f32.bf16.bf16.f32 "
        "{%0,%1,%2,%3}, {%4,%5,%6,%7}, {%8,%9}, {%0,%1,%2,%3};"
        : "+f"(c[0]), "+f"(c[1]), "+f"(c[2]), "+f"(c[3])
        : "r"(a[0]), "r"(a[1]), "r"(a[2]), "r"(a[3]), "r"(b[0]), "r"(b[1]));
}

__device__ __forceinline__ void cp16(uint32_t dst, const void* src) {
    asm volatile("cp.async.cg.shared.global [%0], [%1], 16;"
                 :: "r"(dst), "l"(src) : "memory");
}

// ---------------------------------------------------------------------------
// Kernel 2: persistent, 2 CTAs/SM, double-buffered 128x128 tiles.
// 8 warps: wn = w>>2 (two 64-row bands), wc = w&3 (four 32-col bands).
// ---------------------------------------------------------------------------
extern __shared__ char smem[];

__device__ __forceinline__ void prefetch_tile(uint32_t sb, int stage, int tl,
                                              int t) {
    const int b = tl >> 10, rem = tl & 1023, nb = rem >> 5, mb = rem & 31;
    const unsigned char* a = g_xbf + (size_t)(b * 32 + nb) * 16384;
    const unsigned char* h = g_yhi + (size_t)(b * 32 + mb) * 16384;
    const unsigned char* l = g_ylo + (size_t)(b * 32 + mb) * 16384;
    const uint32_t dst = sb + stage * STAGE;
    const uint32_t o = (uint32_t)t * 16;
#pragma unroll
    for (int i = 0; i < 4; i++) {
        cp16(dst + o + i * 4096, a + o + i * 4096);
        cp16(dst + OFF_BHI + o + i * 4096, h + o + i * 4096);
        cp16(dst + OFF_BLO + o + i * 4096, l + o + i * 4096);
    }
}

__global__ void __launch_bounds__(256, 2)
tile_hmma_kernel(int G) {
    const uint32_t sb = s2u(smem);
    const int t = threadIdx.x, lane = t & 31, w = t >> 5;
    const int wn = w >> 2;            // 0..1 : 64-row band
    const int wc = w & 3;             // 0..3 : 32-col band

    // Per-lane ldmatrix base offsets (bytes, pre-swizzle).
    const int tq = lane >> 3, tr = lane & 7;
    uint32_t aOff[4], bOff[4];
#pragma unroll
    for (int mt = 0; mt < 4; mt++)
        aOff[mt] = (uint32_t)((wn * 64 + mt * 16 + (tq & 1) * 8 + tr) * 128 +
                              (tq >> 1) * 16);
    const int l16 = lane & 15;
#pragma unroll
    for (int nt = 0; nt < 4; nt++)
        bOff[nt] = (uint32_t)((wc * 32 + nt * 8 + (l16 & 7)) * 128 +
                              (l16 >> 3) * 16);

    int tid = blockIdx.x;
    if (tid >= NTILES) return;

    prefetch_tile(sb, 0, tid, t);
    asm volatile("cp.async.commit_group;" ::: "memory");

    int p = 0;
    for (; tid < NTILES; tid += G, p ^= 1) {
        const int nx = tid + G;
        if (nx < NTILES) prefetch_tile(sb, p ^ 1, nx, t);
        asm volatile("cp.async.commit_group;" ::: "memory");
        asm volatile("cp.async.wait_group 1;" ::: "memory");
        __syncthreads();

        const int b = tid >> 10, rem = tid & 1023;
        const int n0 = (rem >> 5) * 128, m0 = (rem & 31) * 128;
        const uint32_t base = sb + p * STAGE;

        float acc[4][4][4];
#pragma unroll
        for (int i = 0; i < 4; i++)
#pragma unroll
            for (int j = 0; j < 4; j++)
#pragma unroll
                for (int e = 0; e < 4; e++) acc[i][j][e] = 0.f;

#pragma unroll
        for (int kk = 0; kk < 4; kk++) {
            const uint32_t kcol = kk * 32;
            uint32_t a[4][4];
#pragma unroll
            for (int mt = 0; mt < 4; mt++) {
                uint32_t addr = base + SWZ(aOff[mt] + kcol);
                asm volatile("ldmatrix.sync.aligned.m8n8.x4.shared.b16 "
                             "{%0,%1,%2,%3}, [%4];"
                             : "=r"(a[mt][0]), "=r"(a[mt][1]),
                               "=r"(a[mt][2]), "=r"(a[mt][3]) : "r"(addr));
            }
#pragma unroll
            for (int ph = 0; ph < 2; ph++) {
                const uint32_t bbase = base + (ph ? OFF_BLO : OFF_BHI);
                uint32_t bf[4][2];
#pragma unroll
                for (int nt = 0; nt < 4; nt++) {
                    uint32_t addr = bbase + SWZ(bOff[nt] + kcol);
                    asm volatile("ldmatrix.sync.aligned.m8n8.x2.shared.b16 "
                                 "{%0,%1}, [%2];"
                                 : "=r"(bf[nt][0]), "=r"(bf[nt][1]) : "r"(addr));
                }
#pragma unroll
                for (int mt = 0; mt < 4; mt++)
#pragma unroll
                    for (int nt = 0; nt < 4; nt++)
                        mma16816(acc[mt][nt], a[mt], bf[nt]);
            }
        }

        // Epilogue (barrier-free): fragment e -> row l/4+(e>>1)*8, col 2*(l%4)+(e&1)
        float x2r[8], y2c[8];
#pragma unroll
        for (int mt = 0; mt < 4; mt++)
#pragma unroll
            for (int s = 0; s < 2; s++)
                x2r[mt * 2 + s] = __ldg(
                    &g_x2[b * NN + n0 + wn * 64 + mt * 16 + (lane >> 2) + s * 8]);
#pragma unroll
        for (int nt = 0; nt < 4; nt++)
#pragma unroll
            for (int e = 0; e < 2; e++)
                y2c[nt * 2 + e] = __ldg(
                    &g_y2[b * MM + m0 + wc * 32 + nt * 8 + 2 * (lane & 3) + e]);

        float rowmin[8], colmin[8];
#pragma unroll
        for (int i = 0; i < 8; i++) { rowmin[i] = FINF; colmin[i] = FINF; }

#pragma unroll
        for (int mt = 0; mt < 4; mt++)
#pragma unroll
            for (int nt = 0; nt < 4; nt++)
#pragma unroll
                for (int e = 0; e < 4; e++) {
                    const int ri = mt * 2 + (e >> 1), cj = nt * 2 + (e & 1);
                    float v = -2.f * acc[mt][nt][e];
                    rowmin[ri] = fminf(rowmin[ri], v + y2c[cj]);
                    colmin[cj] = fminf(colmin[cj], v + x2r[ri]);
                }

#pragma unroll
        for (int off = 1; off <= 2; off <<= 1)
#pragma unroll
            for (int i = 0; i < 8; i++)
                rowmin[i] = fminf(rowmin[i],
                                  __shfl_xor_sync(~0u, rowmin[i], off));
#pragma unroll
        for (int off = 4; off <= 16; off <<= 1)
#pragma unroll
            for (int i = 0; i < 8; i++)
                colmin[i] = fminf(colmin[i],
                                  __shfl_xor_sync(~0u, colmin[i], off));

        if ((lane & 3) == 0) {
#pragma unroll
            for (int mt = 0; mt < 4; mt++)
#pragma unroll
                for (int s = 0; s < 2; s++) {
                    int row = wn * 64 + mt * 16 + (lane >> 2) + s * 8;
                    float v = fmaxf(rowmin[mt * 2 + s] + x2r[mt * 2 + s], 0.f);
                    atomicMin((int*)&g_min_m[b * NN + n0 + row],
                              __float_as_int(v));
                }
        }
        if (lane < 4) {
#pragma unroll
            for (int nt = 0; nt < 4; nt++)
#pragma unroll
                for (int e = 0; e < 2; e++) {
                    int col = wc * 32 + nt * 8 + 2 * lane + e;
                    float v = fmaxf(colmin[nt * 2 + e] + y2c[nt * 2 + e], 0.f);
                    atomicMin((int*)&g_min_n[b * MM + m0 + col],
                              __float_as_int(v));
                }
        }
        __syncthreads();   // protect stage p from next prefetch
    }
}

// ---------------------------------------------------------------------------
// Kernel 3: loss = sum(sqrt(mins)) / (B * 4096)
// ---------------------------------------------------------------------------
__global__ void reduce_kernel(float* __restrict__ out) {
    __shared__ float ssum[1024];
    int t = threadIdx.x;
    float s = 0.f;
    for (int i = t; i < BB * NN; i += 1024)
        s += sqrtf(g_min_m[i]) + sqrtf(g_min_n[i]);
    ssum[t] = s;
    __syncthreads();
#pragma unroll
    for (int off = 512; off > 0; off >>= 1) {
        if (t < off) ssum[t] += ssum[t + off];
        __syncthreads();
    }
    if (t == 0) out[0] = ssum[0] * (1.0f / (BB * NN));
}

// ---------------------------------------------------------------------------
extern "C" void kernel_launch(void* const* d_in, const int* in_sizes, int n_in,
                              void* d_out, int out_size) {
    const float* x = (const float*)d_in[0];
    const float* y = (const float*)d_in[1];
    float* out = (float*)d_out;

    static int nsm = 0;
    if (nsm == 0) {
        if (cudaDeviceGetAttribute(&nsm, cudaDevAttrMultiProcessorCount, 0)
                != cudaSuccess || nsm <= 0)
            nsm = 148;
        cudaFuncSetAttribute(tile_hmma_kernel,
                             cudaFuncAttributeMaxDynamicSharedMemorySize,
                             SMEM_SZ);
    }

    prep_kernel<<<(2 * BB * NN * 16) / 256, 256>>>(x, y);

    int G = 2 * nsm < NTILES ? 2 * nsm : NTILES;
    tile_hmma_kernel<<<G, 256, SMEM_SZ>>>(G);

    reduce_kernel<<<1, 1024>>>(out);
}

// round 11
// speedup vs baseline: 1.3354x; 1.2560x over previous
#include <cuda_runtime.h>
#include <cuda_bf16.h>
#include <math.h>
#include <stdint.h>

#define BB   8
#define NN   4096
#define MM   4096
#define KK   64

#define FINF __int_as_float(0x7F800000)

__device__ float g_min_m[BB * NN];
__device__ float g_min_n[BB * MM];
__device__ float g_x2[BB * NN];
__device__ float g_y2[BB * MM];

// Pre-converted, pre-swizzled 16 KB tile images (smem-ready, 128 rows each).
__device__ __align__(16384) unsigned char g_xbf[BB * NN * 128];
__device__ __align__(16384) unsigned char g_ybf[BB * MM * 128];

__device__ __forceinline__ uint32_t s2u(const void* p) {
    uint32_t a;
    asm("{ .reg .u64 t; cvta.to.shared.u64 t, %1; cvt.u32.u64 %0, t; }"
        : "=r"(a) : "l"(p));
    return a;
}

#define SWZ(o) ((o) ^ (((o) >> 3) & 0x70))

// SMEM: A tile [0,16K), B tile [16K,32K)
#define SM_B    16384
#define SMEM_SZ 32768

// ---------------------------------------------------------------------------
// Kernel 1: convert + swizzle-pack + norms + min-init. 16 lanes per row.
// ---------------------------------------------------------------------------
__global__ void prep_kernel(const float* __restrict__ x,
                            const float* __restrict__ y) {
    const int gid = blockIdx.x * blockDim.x + threadIdx.x;
    const int row = gid >> 4, k4 = gid & 15;
    const int R = BB * NN;
    const bool isx = row < R;
    const int r = isx ? row : row - R;

    const float4 v = ((const float4*)((isx ? x : y) + (size_t)r * KK))[k4];
    const uint32_t off = (uint32_t)(r >> 7) * 16384u +
                         SWZ((uint32_t)((r & 127) * 128 + k4 * 8));

    __nv_bfloat162 p01 = __floats2bfloat162_rn(v.x, v.y);
    __nv_bfloat162 p23 = __floats2bfloat162_rn(v.z, v.w);
    uint2 h;
    h.x = *reinterpret_cast<uint32_t*>(&p01);
    h.y = *reinterpret_cast<uint32_t*>(&p23);
    *(uint2*)((isx ? g_xbf : g_ybf) + off) = h;

    float s = v.x * v.x + v.y * v.y + v.z * v.z + v.w * v.w;
    s += __shfl_xor_sync(~0u, s, 1);
    s += __shfl_xor_sync(~0u, s, 2);
    s += __shfl_xor_sync(~0u, s, 4);
    s += __shfl_xor_sync(~0u, s, 8);
    if (k4 == 0) {
        if (isx) { g_x2[r] = s; g_min_m[r] = FINF; }
        else     { g_y2[r] = s; g_min_n[r] = FINF; }
    }
}

__device__ __forceinline__ void mma16816(float* c, const uint32_t* a,
                                         const uint32_t* b) {
    asm volatile(
        "mma.sync.aligned.m16n8k16.row.col.f32.bf16.bf16.f32 "
        "{%0,%1,%2,%3}, {%4,%5,%6,%7}, {%8,%9}, {%0,%1,%2,%3};"
        : "+f"(c[0]), "+f"(c[1]), "+f"(c[2]), "+f"(c[3])
        : "r"(a[0]), "r"(a[1]), "r"(a[2]), "r"(a[3]), "r"(b[0]), "r"(b[1]));
}

__device__ __forceinline__ void cp16(uint32_t dst, const void* src) {
    asm volatile("cp.async.cg.shared.global [%0], [%1], 16;"
                 :: "r"(dst), "l"(src) : "memory");
}

// ---------------------------------------------------------------------------
// Kernel 2: 128x128 tile per CTA, single-pass bf16 HMMA, barrier-free epilogue.
// 8 warps: wn = w>>2 (two 64-row bands), wc = w&3 (four 32-col bands).
// ---------------------------------------------------------------------------
extern __shared__ char smem[];

__global__ void __launch_bounds__(256, 2)
tile_hmma_kernel() {
    const uint32_t sb = s2u(smem);
    const int t = threadIdx.x, lane = t & 31, w = t >> 5;
    const int wn = w >> 2;
    const int wc = w & 3;
    const int b = blockIdx.z, n0 = blockIdx.y * 128, m0 = blockIdx.x * 128;

    // Async-copy the two 16 KB tile images.
    {
        const unsigned char* asrc = g_xbf + (size_t)(b * 32 + blockIdx.y) * 16384;
        const unsigned char* bsrc = g_ybf + (size_t)(b * 32 + blockIdx.x) * 16384;
        const uint32_t o = (uint32_t)t * 16;
#pragma unroll
        for (int i = 0; i < 4; i++) {
            cp16(sb + o + i * 4096, asrc + o + i * 4096);
            cp16(sb + SM_B + o + i * 4096, bsrc + o + i * 4096);
        }
        asm volatile("cp.async.commit_group;" ::: "memory");
    }

    // Per-lane ldmatrix base offsets (bytes, pre-swizzle).
    const int tq = lane >> 3, tr = lane & 7;
    uint32_t aOff[4], bOff[4];
#pragma unroll
    for (int mt = 0; mt < 4; mt++)
        aOff[mt] = (uint32_t)((wn * 64 + mt * 16 + (tq & 1) * 8 + tr) * 128 +
                              (tq >> 1) * 16);
    const int l16 = lane & 15;
#pragma unroll
    for (int nt = 0; nt < 4; nt++)
        bOff[nt] = (uint32_t)((wc * 32 + nt * 8 + (l16 & 7)) * 128 +
                              (l16 >> 3) * 16);

    // Epilogue scalars (hide latency under the load wait).
    float x2r[8], y2c[8];
#pragma unroll
    for (int mt = 0; mt < 4; mt++)
#pragma unroll
        for (int s = 0; s < 2; s++)
            x2r[mt * 2 + s] = __ldg(
                &g_x2[b * NN + n0 + wn * 64 + mt * 16 + (lane >> 2) + s * 8]);
#pragma unroll
    for (int nt = 0; nt < 4; nt++)
#pragma unroll
        for (int e = 0; e < 2; e++)
            y2c[nt * 2 + e] = __ldg(
                &g_y2[b * MM + m0 + wc * 32 + nt * 8 + 2 * (lane & 3) + e]);

    float acc[4][4][4];
#pragma unroll
    for (int i = 0; i < 4; i++)
#pragma unroll
        for (int j = 0; j < 4; j++)
#pragma unroll
            for (int e = 0; e < 4; e++) acc[i][j][e] = 0.f;

    asm volatile("cp.async.wait_group 0;" ::: "memory");
    __syncthreads();

#pragma unroll
    for (int kk = 0; kk < 4; kk++) {
        const uint32_t kcol = kk * 32;
        uint32_t a[4][4], bf[4][2];
#pragma unroll
        for (int mt = 0; mt < 4; mt++) {
            uint32_t addr = sb + SWZ(aOff[mt] + kcol);
            asm volatile("ldmatrix.sync.aligned.m8n8.x4.shared.b16 "
                         "{%0,%1,%2,%3}, [%4];"
                         : "=r"(a[mt][0]), "=r"(a[mt][1]),
                           "=r"(a[mt][2]), "=r"(a[mt][3]) : "r"(addr));
        }
#pragma unroll
        for (int nt = 0; nt < 4; nt++) {
            uint32_t addr = sb + SM_B + SWZ(bOff[nt] + kcol);
            asm volatile("ldmatrix.sync.aligned.m8n8.x2.shared.b16 "
                         "{%0,%1}, [%2];"
                         : "=r"(bf[nt][0]), "=r"(bf[nt][1]) : "r"(addr));
        }
#pragma unroll
        for (int mt = 0; mt < 4; mt++)
#pragma unroll
            for (int nt = 0; nt < 4; nt++)
                mma16816(acc[mt][nt], a[mt], bf[nt]);
    }

    // Barrier-free epilogue. Fragment e -> row l/4+(e>>1)*8, col 2*(l%4)+(e&1)
    float rowmin[8], colmin[8];
#pragma unroll
    for (int i = 0; i < 8; i++) { rowmin[i] = FINF; colmin[i] = FINF; }

#pragma unroll
    for (int mt = 0; mt < 4; mt++)
#pragma unroll
        for (int nt = 0; nt < 4; nt++)
#pragma unroll
            for (int e = 0; e < 4; e++) {
                const int ri = mt * 2 + (e >> 1), cj = nt * 2 + (e & 1);
                float v = -2.f * acc[mt][nt][e];
                rowmin[ri] = fminf(rowmin[ri], v + y2c[cj]);
                colmin[cj] = fminf(colmin[cj], v + x2r[ri]);
            }

#pragma unroll
    for (int off = 1; off <= 2; off <<= 1)
#pragma unroll
        for (int i = 0; i < 8; i++)
            rowmin[i] = fminf(rowmin[i], __shfl_xor_sync(~0u, rowmin[i], off));
#pragma unroll
    for (int off = 4; off <= 16; off <<= 1)
#pragma unroll
        for (int i = 0; i < 8; i++)
            colmin[i] = fminf(colmin[i], __shfl_xor_sync(~0u, colmin[i], off));

    if ((lane & 3) == 0) {
#pragma unroll
        for (int mt = 0; mt < 4; mt++)
#pragma unroll
            for (int s = 0; s < 2; s++) {
                int row = wn * 64 + mt * 16 + (lane >> 2) + s * 8;
                float v = fmaxf(rowmin[mt * 2 + s] + x2r[mt * 2 + s], 0.f);
                atomicMin((int*)&g_min_m[b * NN + n0 + row], __float_as_int(v));
            }
    }
    if (lane < 4) {
#pragma unroll
        for (int nt = 0; nt < 4; nt++)
#pragma unroll
            for (int e = 0; e < 2; e++) {
                int col = wc * 32 + nt * 8 + 2 * lane + e;
                float v = fmaxf(colmin[nt * 2 + e] + y2c[nt * 2 + e], 0.f);
                atomicMin((int*)&g_min_n[b * MM + m0 + col], __float_as_int(v));
            }
    }
}

// ---------------------------------------------------------------------------
// Kernel 3: loss = sum(sqrt(mins)) / (B * 4096)
// ---------------------------------------------------------------------------
__global__ void reduce_kernel(float* __restrict__ out) {
    __shared__ float ssum[1024];
    int t = threadIdx.x;
    float s = 0.f;
    for (int i = t; i < BB * NN; i += 1024)
        s += sqrtf(g_min_m[i]) + sqrtf(g_min_n[i]);
    ssum[t] = s;
    __syncthreads();
#pragma unroll
    for (int off = 512; off > 0; off >>= 1) {
        if (t < off) ssum[t] += ssum[t + off];
        __syncthreads();
    }
    if (t == 0) out[0] = ssum[0] * (1.0f / (BB * NN));
}

// ---------------------------------------------------------------------------
extern "C" void kernel_launch(void* const* d_in, const int* in_sizes, int n_in,
                              void* d_out, int out_size) {
    const float* x = (const float*)d_in[0];
    const float* y = (const float*)d_in[1];
    float* out = (float*)d_out;

    cudaFuncSetAttribute(tile_hmma_kernel,
                         cudaFuncAttributeMaxDynamicSharedMemorySize, SMEM_SZ);

    prep_kernel<<<(2 * BB * NN * 16) / 256, 256>>>(x, y);

    dim3 grid(MM / 128, NN / 128, BB);
    tile_hmma_kernel<<<grid, 256, SMEM_SZ>>>();

    reduce_kernel<<<1, 1024>>>(out);
}